// round 5
// baseline (speedup 1.0000x reference)
#include <cuda_runtime.h>
#include <cstdint>

#define D_MODEL 1024
#define N_HEAD 16
#define HEAD_DIM 64
#define B_SZ 4
#define TQ 2048
#define TK 8192
#define STRIDE 16
#define L_CTX 512

__device__ float g_Qh[(size_t)B_SZ * N_HEAD * TQ * HEAD_DIM];
__device__ float g_Kh[(size_t)B_SZ * N_HEAD * L_CTX * HEAD_DIM];
__device__ float g_Vh[(size_t)B_SZ * N_HEAD * L_CTX * HEAD_DIM];
__device__ float g_ctx[(size_t)B_SZ * TQ * D_MODEL];

// ---------------------------------------------------------------------------
__device__ __forceinline__ float tf32_round(float x) {
    uint32_t u;
    asm("cvt.rna.tf32.f32 %0, %1;" : "=r"(u) : "f"(x));
    return __uint_as_float(u);
}

__device__ __forceinline__ void mma_tf32(float* c, const uint32_t* a,
                                         uint32_t b0, uint32_t b1) {
    asm volatile(
        "mma.sync.aligned.m16n8k8.row.col.f32.tf32.tf32.f32 "
        "{%0,%1,%2,%3}, {%4,%5,%6,%7}, {%8,%9}, {%0,%1,%2,%3};\n"
        : "+f"(c[0]), "+f"(c[1]), "+f"(c[2]), "+f"(c[3])
        : "r"(a[0]), "r"(a[1]), "r"(a[2]), "r"(a[3]), "r"(b0), "r"(b1));
}

// ---------------------------------------------------------------------------
// tf32 GEMM, fragment-major smem, 2-stage ping-pong (1 sync/iter).
// MODE 0: Q proj, 1: K sliced, 2: V sliced, 3: O proj.
// Block 128xBN, BK=32, 256 threads (8 warps 4Mx2N).
// AF stage: [ks4][mfrag8][lane32]float4 ; BF stage: [ks4][nfrag BN/8][lane32]float2
// ---------------------------------------------------------------------------
template <int BN, int MODE>
__global__ void __launch_bounds__(256, 2)
tf32_gemm_kernel(const float* __restrict__ Ain,
                 const float* __restrict__ W,
                 const float* __restrict__ bias,
                 float* __restrict__ Cout) {
    extern __shared__ float dynsm[];
    constexpr int AF_SZ = 4 * 8 * 32 * 4;        // 4096 floats
    constexpr int BF_SZ = 4 * (BN / 8) * 32 * 2; // BN*32 floats
    float* AF[2] = {dynsm, dynsm + AF_SZ + BF_SZ};
    float* BF[2] = {dynsm + AF_SZ, dynsm + 2 * AF_SZ + BF_SZ};

    const int tid = threadIdx.x;
    const int lane = tid & 31, warp = tid >> 5;
    const int gid = lane >> 2, tig = lane & 3;
    const int lanek = tig * 8 + gid;

    int m0, bh = 0, h = 0, n_base = 0;
    const float* A;
    if (MODE == 1 || MODE == 2) {
        bh = blockIdx.y; int b = bh >> 4; h = bh & 15;
        m0 = blockIdx.x * 128;
        A = Ain + (size_t)b * TK * D_MODEL;
        n_base = h * 64;
    } else {
        m0 = blockIdx.y * 128;
        n_base = blockIdx.x * BN;
        A = (MODE == 3) ? g_ctx : Ain;
    }

    const int wmf = (warp >> 1) * 2;              // m-frag base (of 8)
    const int wnf = (warp & 1) * (BN / 16);       // n-frag base (of BN/8)
    constexpr int NF = BN / 16;
    constexpr int WL = BN / 32;
    constexpr int NB8 = BN / 8;

    float acc[2][NF][4] = {};
    float4 avS[4];
    float4 wvS[WL];

    auto LOAD = [&](int k0) {
#pragma unroll
        for (int i = 0; i < 4; i++) {
            int idx = tid + i * 256;
            int row = idx >> 3, kc = (idx & 7) * 4;
            int grow = (MODE == 1 || MODE == 2) ? (h + STRIDE * (m0 + row))
                                                : (m0 + row);
            avS[i] = *(const float4*)(A + (size_t)grow * D_MODEL + k0 + kc);
        }
#pragma unroll
        for (int i = 0; i < WL; i++) {
            int idx = tid + i * 256;
            int nrow = idx >> 3, kc = (idx & 7) * 4;
            wvS[i] = *(const float4*)(W + (size_t)(n_base + nrow) * D_MODEL + k0 + kc);
        }
    };
    auto STORE = [&](int s) {
#pragma unroll
        for (int i = 0; i < 4; i++) {
            int idx = tid + i * 256;
            int row = idx >> 3, kc = (idx & 7) * 4;
            int mfrag = row >> 4, half = (row >> 3) & 1, gd = row & 7;
            float vv[4] = {avS[i].x, avS[i].y, avS[i].z, avS[i].w};
#pragma unroll
            for (int e = 0; e < 4; e++) {
                int k = kc + e;
                int ks = k >> 3, ch = (k >> 2) & 1, tg = k & 3;
                AF[s][(((ks * 8 + mfrag) * 32) + tg * 8 + gd) * 4 + half + 2 * ch] =
                    tf32_round(vv[e]);
            }
        }
#pragma unroll
        for (int i = 0; i < WL; i++) {
            int idx = tid + i * 256;
            int nrow = idx >> 3, kc = (idx & 7) * 4;
            int nfrag = nrow >> 3, gd = nrow & 7;
            float vv[4] = {wvS[i].x, wvS[i].y, wvS[i].z, wvS[i].w};
#pragma unroll
            for (int e = 0; e < 4; e++) {
                int k = kc + e;
                int ks = k >> 3, ch = (k >> 2) & 1, tg = k & 3;
                BF[s][(((ks * NB8 + nfrag) * 32) + tg * 8 + gd) * 2 + ch] =
                    tf32_round(vv[e]);
            }
        }
    };
    auto MMA = [&](int s) {
#pragma unroll
        for (int ks = 0; ks < 4; ks++) {
            float4 a0 = *(const float4*)&AF[s][((ks * 8 + wmf) * 32 + lanek) * 4];
            float4 a1 = *(const float4*)&AF[s][((ks * 8 + wmf + 1) * 32 + lanek) * 4];
            uint32_t af0[4] = {__float_as_uint(a0.x), __float_as_uint(a0.y),
                               __float_as_uint(a0.z), __float_as_uint(a0.w)};
            uint32_t af1[4] = {__float_as_uint(a1.x), __float_as_uint(a1.y),
                               __float_as_uint(a1.z), __float_as_uint(a1.w)};
#pragma unroll
            for (int ni = 0; ni < NF; ni++) {
                float2 bv = *(const float2*)
                    &BF[s][((ks * NB8 + wnf + ni) * 32 + lanek) * 2];
                uint32_t b0 = __float_as_uint(bv.x), b1 = __float_as_uint(bv.y);
                mma_tf32(acc[0][ni], af0, b0, b1);
                mma_tf32(acc[1][ni], af1, b0, b1);
            }
        }
    };

    LOAD(0);
    STORE(0);
    __syncthreads();
    int s = 0;
#pragma unroll 1
    for (int k0 = 32; k0 < D_MODEL; k0 += 32) {
        LOAD(k0);
        MMA(s);
        STORE(s ^ 1);
        __syncthreads();
        s ^= 1;
    }
    MMA(s);

    // --- writeback ---
#pragma unroll
    for (int mi = 0; mi < 2; mi++) {
#pragma unroll
        for (int ni = 0; ni < NF; ni++) {
#pragma unroll
            for (int r = 0; r < 4; r++) {
                int ml = (wmf + mi) * 16 + gid + ((r >> 1) ? 8 : 0);
                int nl = (wnf + ni) * 8 + 2 * tig + (r & 1);
                float v = acc[mi][ni][r];
                if (MODE == 0) {
                    int m = m0 + ml;
                    int n = n_base + nl;
                    int bb = m >> 11, tq = m & 2047;
                    int hh = n >> 6, d = n & 63;
                    g_Qh[(((size_t)bb * N_HEAD + hh) * TQ + tq) * HEAD_DIM + d] =
                        v + bias[n];
                } else if (MODE == 1) {
                    g_Kh[((size_t)bh * L_CTX + m0 + ml) * HEAD_DIM + nl] =
                        v + bias[n_base + nl];
                } else if (MODE == 2) {
                    g_Vh[((size_t)bh * L_CTX + m0 + ml) * HEAD_DIM + nl] =
                        v + bias[n_base + nl];
                } else {
                    Cout[(size_t)(m0 + ml) * D_MODEL + n_base + nl] =
                        v + bias[n_base + nl];
                }
            }
        }
    }
}

// ---------------------------------------------------------------------------
// Flash attention, fragment-major conflict-free K/V smem.
// Block = 64 q x one (b,h), 128 threads / 4 warps, warp owns 16 rows.
// KF: [ks8][ni8][lane32] float4 {hi_c0,hi_c1,lo_c0,lo_c1}
// VF: [ks8][ni8][lane32] float2 {b0,b1}
// ---------------------------------------------------------------------------
#define AT_THREADS 128
#define OFF_QF   0
#define OFF_KF   4096
#define OFF_VF   12288
#define OFF_P    16384
#define OFF_MSK  (OFF_P + 4 * 16 * 68)
#define AT_SMEM_BYTES ((OFF_MSK + 512) * 4)

__global__ void __launch_bounds__(128, 2)
attn_kernel(const int* __restrict__ mask) {
    extern __shared__ float sm[];
    float* Qf = sm + OFF_QF;
    float* KF = sm + OFF_KF;
    float* VF = sm + OFF_VF;
    float* Pw = sm + OFF_P;
    int*   msk = (int*)(sm + OFF_MSK);

    const int bh = blockIdx.y;
    const int b = bh >> 4, h = bh & 15;
    const int q0 = blockIdx.x * 64;
    const int tid = threadIdx.x;
    const int lane = tid & 31, warp = tid >> 5;
    const int gid = lane >> 2, tig = lane & 3;
    const int lanek = tig * 8 + gid;

    for (int i = tid; i < L_CTX; i += AT_THREADS)
        msk[i] = mask[(size_t)b * TK + h + STRIDE * i];

    // Q tile -> fragment-major smem (fp32; hi/lo at use)
    const float* Qb = g_Qh + ((size_t)bh * TQ + q0) * HEAD_DIM;
#pragma unroll
    for (int i = 0; i < 8; i++) {
        int idx = tid + i * AT_THREADS;
        int row = idx >> 4;
        int dc = (idx & 15) * 4;
        float4 v = *(const float4*)(Qb + row * 64 + dc);
        int mg = row >> 4, mh = (row >> 3) & 1, g = row & 7;
        float vv[4] = {v.x, v.y, v.z, v.w};
#pragma unroll
        for (int e = 0; e < 4; e++) {
            int d = dc + e;
            int ks = d >> 3, kh = (d >> 2) & 1, tg = d & 3;
            int ln = ((g * 4 + tg) + ks * 2) & 31;
            Qf[((ks * 4 + mg) * 32 + ln) * 4 + kh * 2 + mh] = vv[e];
        }
    }

    const float* Kb = g_Kh + (size_t)bh * L_CTX * HEAD_DIM;
    const float* Vb = g_Vh + (size_t)bh * L_CTX * HEAD_DIM;
    float* Pp = Pw + warp * (16 * 68);

    float oacc[8][4] = {};
    float M0 = -1e30f, M1 = -1e30f, L0 = 0.f, L1 = 0.f;

#pragma unroll 1
    for (int lt = 0; lt < 8; lt++) {
        __syncthreads();
        // K tile: r = key row (n), d = head dim (k)
#pragma unroll
        for (int i = 0; i < 8; i++) {
            int idx = tid + i * AT_THREADS;
            int r = idx >> 4;
            int dc = (idx & 15) * 4;
            int ni = r >> 3, gd = r & 7;
            float4 kv = *(const float4*)(Kb + (size_t)(lt * 64 + r) * 64 + dc);
            float kk[4] = {kv.x, kv.y, kv.z, kv.w};
#pragma unroll
            for (int e = 0; e < 4; e++) {
                int d = dc + e;
                int ks = d >> 3, ch = (d >> 2) & 1, tg = d & 3;
                int base = ((ks * 8 + ni) * 32 + tg * 8 + gd) * 4;
                float hi = tf32_round(kk[e]);
                KF[base + ch] = hi;
                KF[base + 2 + ch] = tf32_round(kk[e] - hi);
            }
            // V tile: r = l (k-dim), d = head dim (n)
            float4 vv = *(const float4*)(Vb + (size_t)(lt * 64 + r) * 64 + dc);
            float vl[4] = {vv.x, vv.y, vv.z, vv.w};
            int vks = r >> 3, vslot = (r >> 2) & 1, vtg = r & 3;
#pragma unroll
            for (int e = 0; e < 4; e++) {
                int d = dc + e;
                int vni = d >> 3, vgd = d & 7;
                VF[((vks * 8 + vni) * 32 + vtg * 8 + vgd) * 2 + vslot] =
                    tf32_round(vl[e]);
            }
        }
        __syncthreads();

        // ---- S = Q K^T (3x tf32 split) ----
        float sacc[8][4] = {};
#pragma unroll
        for (int ks = 0; ks < 8; ks++) {
            float4 qv = *(const float4*)&Qf[((ks * 4 + warp) * 32 +
                                             ((lane + ks * 2) & 31)) * 4];
            uint32_t ah[4], al[4];
            float q4[4] = {qv.x, qv.y, qv.z, qv.w};
#pragma unroll
            for (int j = 0; j < 4; j++) {
                float hi = tf32_round(q4[j]);
                ah[j] = __float_as_uint(hi);
                al[j] = __float_as_uint(tf32_round(q4[j] - hi));
            }
#pragma unroll
            for (int ni = 0; ni < 8; ni++) {
                float4 kk = *(const float4*)&KF[((ks * 8 + ni) * 32 + lanek) * 4];
                uint32_t b0 = __float_as_uint(kk.x), b1 = __float_as_uint(kk.y);
                uint32_t c0 = __float_as_uint(kk.z), c1 = __float_as_uint(kk.w);
                mma_tf32(sacc[ni], ah, b0, b1);
                mma_tf32(sacc[ni], al, b0, b1);
                mma_tf32(sacc[ni], ah, c0, c1);
            }
        }

        // ---- scale + mask + online softmax ----
        float mt0 = -1e30f, mt1 = -1e30f;
#pragma unroll
        for (int ni = 0; ni < 8; ni++) {
            int c = lt * 64 + ni * 8 + 2 * tig;
            bool z0 = (msk[c] == 0), z1 = (msk[c + 1] == 0);
            sacc[ni][0] = z0 ? -1e9f : sacc[ni][0] * 0.125f;
            sacc[ni][1] = z1 ? -1e9f : sacc[ni][1] * 0.125f;
            sacc[ni][2] = z0 ? -1e9f : sacc[ni][2] * 0.125f;
            sacc[ni][3] = z1 ? -1e9f : sacc[ni][3] * 0.125f;
            mt0 = fmaxf(mt0, fmaxf(sacc[ni][0], sacc[ni][1]));
            mt1 = fmaxf(mt1, fmaxf(sacc[ni][2], sacc[ni][3]));
        }
        mt0 = fmaxf(mt0, __shfl_xor_sync(0xffffffffu, mt0, 1));
        mt0 = fmaxf(mt0, __shfl_xor_sync(0xffffffffu, mt0, 2));
        mt1 = fmaxf(mt1, __shfl_xor_sync(0xffffffffu, mt1, 1));
        mt1 = fmaxf(mt1, __shfl_xor_sync(0xffffffffu, mt1, 2));

        float Mn0 = fmaxf(M0, mt0), Mn1 = fmaxf(M1, mt1);
        float f0 = __expf(M0 - Mn0), f1 = __expf(M1 - Mn1);
        float s0 = 0.f, s1 = 0.f;
#pragma unroll
        for (int ni = 0; ni < 8; ni++) {
            int cc = ni * 8 + 2 * tig;
            float p00 = __expf(sacc[ni][0] - Mn0);
            float p01 = __expf(sacc[ni][1] - Mn0);
            float p10 = __expf(sacc[ni][2] - Mn1);
            float p11 = __expf(sacc[ni][3] - Mn1);
            s0 += p00 + p01; s1 += p10 + p11;
            Pp[gid * 68 + cc]           = tf32_round(p00);
            Pp[gid * 68 + cc + 1]       = tf32_round(p01);
            Pp[(gid + 8) * 68 + cc]     = tf32_round(p10);
            Pp[(gid + 8) * 68 + cc + 1] = tf32_round(p11);
        }
        s0 += __shfl_xor_sync(0xffffffffu, s0, 1);
        s0 += __shfl_xor_sync(0xffffffffu, s0, 2);
        s1 += __shfl_xor_sync(0xffffffffu, s1, 1);
        s1 += __shfl_xor_sync(0xffffffffu, s1, 2);
        L0 = L0 * f0 + s0; L1 = L1 * f1 + s1;
        M0 = Mn0; M1 = Mn1;
#pragma unroll
        for (int ni = 0; ni < 8; ni++) {
            oacc[ni][0] *= f0; oacc[ni][1] *= f0;
            oacc[ni][2] *= f1; oacc[ni][3] *= f1;
        }
        __syncwarp();

        // ---- O += P V ----
#pragma unroll
        for (int ks = 0; ks < 8; ks++) {
            uint32_t a[4];
            a[0] = __float_as_uint(Pp[gid * 68 + ks * 8 + tig]);
            a[1] = __float_as_uint(Pp[(gid + 8) * 68 + ks * 8 + tig]);
            a[2] = __float_as_uint(Pp[gid * 68 + ks * 8 + tig + 4]);
            a[3] = __float_as_uint(Pp[(gid + 8) * 68 + ks * 8 + tig + 4]);
#pragma unroll
            for (int ni = 0; ni < 8; ni++) {
                float2 bv = *(const float2*)&VF[((ks * 8 + ni) * 32 + lanek) * 2];
                mma_tf32(oacc[ni], a,
                         __float_as_uint(bv.x), __float_as_uint(bv.y));
            }
        }
    }

    // ---- epilogue ----
    float inv0 = 1.0f / L0, inv1 = 1.0f / L1;
    int r0 = q0 + warp * 16 + gid;
#pragma unroll
    for (int ni = 0; ni < 8; ni++) {
        int col = h * 64 + ni * 8 + 2 * tig;
        size_t base0 = ((size_t)b * TQ + r0) * D_MODEL + col;
        *(float2*)&g_ctx[base0] =
            make_float2(oacc[ni][0] * inv0, oacc[ni][1] * inv0);
        *(float2*)&g_ctx[base0 + (size_t)8 * D_MODEL] =
            make_float2(oacc[ni][2] * inv1, oacc[ni][3] * inv1);
    }
}

// ---------------------------------------------------------------------------
extern "C" void kernel_launch(void* const* d_in, const int* in_sizes, int n_in,
                              void* d_out, int out_size) {
    const float* q        = (const float*)d_in[0];
    const float* k        = (const float*)d_in[1];
    const float* v        = (const float*)d_in[2];
    const int*   src_mask = (const int*)d_in[3];
    const float* w_q      = (const float*)d_in[4];
    const float* b_q      = (const float*)d_in[5];
    const float* w_k      = (const float*)d_in[6];
    const float* b_k      = (const float*)d_in[7];
    const float* w_v      = (const float*)d_in[8];
    const float* b_v      = (const float*)d_in[9];
    const float* w_o      = (const float*)d_in[10];
    const float* b_o      = (const float*)d_in[11];
    float* out = (float*)d_out;

    constexpr int SMEM_128 = 2 * (4096 + 128 * 32) * 4;  // 65536
    constexpr int SMEM_64  = 2 * (4096 + 64 * 32) * 4;   // 49152

    cudaFuncSetAttribute(attn_kernel,
                         cudaFuncAttributeMaxDynamicSharedMemorySize,
                         AT_SMEM_BYTES);
    cudaFuncSetAttribute(tf32_gemm_kernel<128, 0>,
                         cudaFuncAttributeMaxDynamicSharedMemorySize, SMEM_128);
    cudaFuncSetAttribute(tf32_gemm_kernel<128, 3>,
                         cudaFuncAttributeMaxDynamicSharedMemorySize, SMEM_128);
    cudaFuncSetAttribute(tf32_gemm_kernel<64, 1>,
                         cudaFuncAttributeMaxDynamicSharedMemorySize, SMEM_64);
    cudaFuncSetAttribute(tf32_gemm_kernel<64, 2>,
                         cudaFuncAttributeMaxDynamicSharedMemorySize, SMEM_64);

    tf32_gemm_kernel<128, 0><<<dim3(D_MODEL / 128, (B_SZ * TQ) / 128), 256,
                               SMEM_128>>>(q, w_q, b_q, nullptr);
    tf32_gemm_kernel<64, 1><<<dim3(L_CTX / 128, B_SZ * N_HEAD), 256,
                              SMEM_64>>>(k, w_k, b_k, nullptr);
    tf32_gemm_kernel<64, 2><<<dim3(L_CTX / 128, B_SZ * N_HEAD), 256,
                              SMEM_64>>>(v, w_v, b_v, nullptr);

    attn_kernel<<<dim3(TQ / 64, B_SZ * N_HEAD), 128, AT_SMEM_BYTES>>>(src_mask);

    tf32_gemm_kernel<128, 3><<<dim3(D_MODEL / 128, (B_SZ * TQ) / 128), 256,
                               SMEM_128>>>(nullptr, w_o, b_o, out);
}

// round 6
// speedup vs baseline: 1.4630x; 1.4630x over previous
#include <cuda_runtime.h>
#include <cstdint>

#define D_MODEL 1024
#define N_HEAD 16
#define HEAD_DIM 64
#define B_SZ 4
#define TQ 2048
#define TK 8192
#define STRIDE 16
#define L_CTX 512

__device__ float g_Qh[(size_t)B_SZ * N_HEAD * TQ * HEAD_DIM];
__device__ float g_Kh[(size_t)B_SZ * N_HEAD * L_CTX * HEAD_DIM];
__device__ float g_Vh[(size_t)B_SZ * N_HEAD * L_CTX * HEAD_DIM];
__device__ float g_ctx[(size_t)B_SZ * TQ * D_MODEL];

// ---------------------------------------------------------------------------
__device__ __forceinline__ float tf32_round(float x) {
    uint32_t u;
    asm("cvt.rna.tf32.f32 %0, %1;" : "=r"(u) : "f"(x));
    return __uint_as_float(u);
}

__device__ __forceinline__ void mma_tf32(float* c, const uint32_t* a,
                                         uint32_t b0, uint32_t b1) {
    asm volatile(
        "mma.sync.aligned.m16n8k8.row.col.f32.tf32.tf32.f32 "
        "{%0,%1,%2,%3}, {%4,%5,%6,%7}, {%8,%9}, {%0,%1,%2,%3};\n"
        : "+f"(c[0]), "+f"(c[1]), "+f"(c[2]), "+f"(c[3])
        : "r"(a[0]), "r"(a[1]), "r"(a[2]), "r"(a[3]), "r"(b0), "r"(b1));
}

// ---------------------------------------------------------------------------
// tf32 GEMM: R4 layout ([k][row] smem, same LOAD/STORE/MMA), now 2-stage
// ping-pong with ONE sync per k-iter.
// MODE 0: Q proj, 1: K sliced, 2: V sliced, 3: O proj.
// ---------------------------------------------------------------------------
template <int BN, int MODE>
__global__ void __launch_bounds__(256, 2)
tf32_gemm_kernel(const float* __restrict__ Ain,
                 const float* __restrict__ W,
                 const float* __restrict__ bias,
                 float* __restrict__ Cout) {
    extern __shared__ float dsm[];
    constexpr int ASTAGE = 32 * 132;
    constexpr int WSTRIDE = BN + 4;
    constexpr int WSTAGE = 32 * WSTRIDE;
    float* Asb[2] = {dsm, dsm + ASTAGE + WSTAGE};
    float* Wsb[2] = {dsm + ASTAGE, dsm + 2 * ASTAGE + WSTAGE};

    const int tid = threadIdx.x;
    const int lane = tid & 31, warp = tid >> 5;
    const int gid = lane >> 2, tig = lane & 3;

    int m0, bh = 0, h = 0, n_base = 0;
    const float* A;
    if (MODE == 1 || MODE == 2) {
        bh = blockIdx.y; int b = bh >> 4; h = bh & 15;
        m0 = blockIdx.x * 128;
        A = Ain + (size_t)b * TK * D_MODEL;
        n_base = h * 64;
    } else {
        m0 = blockIdx.y * 128;
        n_base = blockIdx.x * BN;
        A = (MODE == 3) ? g_ctx : Ain;
    }

    const int wm = (warp >> 1) * 32;
    const int wn = (warp & 1) * (BN / 2);
    constexpr int NF = BN / 16;
    constexpr int WL = BN / 32;

    float acc[2][NF][4] = {};
    float4 avS[4];
    float4 wvS[WL];

    auto LOAD = [&](int k0) {
#pragma unroll
        for (int i = 0; i < 4; i++) {
            int idx = tid + i * 256;
            int row = idx >> 3, kc = (idx & 7) * 4;
            int grow = (MODE == 1 || MODE == 2) ? (h + STRIDE * (m0 + row))
                                                : (m0 + row);
            avS[i] = *(const float4*)(A + (size_t)grow * D_MODEL + k0 + kc);
        }
#pragma unroll
        for (int i = 0; i < WL; i++) {
            int idx = tid + i * 256;
            int nrow = idx >> 3, kc = (idx & 7) * 4;
            wvS[i] = *(const float4*)(W + (size_t)(n_base + nrow) * D_MODEL + k0 + kc);
        }
    };
    auto STORE = [&](int s) {
        float* As = Asb[s];
        float* Ws = Wsb[s];
#pragma unroll
        for (int i = 0; i < 4; i++) {
            int idx = tid + i * 256;
            int row = idx >> 3, kc = (idx & 7) * 4;
            As[(kc + 0) * 132 + row] = tf32_round(avS[i].x);
            As[(kc + 1) * 132 + row] = tf32_round(avS[i].y);
            As[(kc + 2) * 132 + row] = tf32_round(avS[i].z);
            As[(kc + 3) * 132 + row] = tf32_round(avS[i].w);
        }
#pragma unroll
        for (int i = 0; i < WL; i++) {
            int idx = tid + i * 256;
            int nrow = idx >> 3, kc = (idx & 7) * 4;
            Ws[(kc + 0) * WSTRIDE + nrow] = tf32_round(wvS[i].x);
            Ws[(kc + 1) * WSTRIDE + nrow] = tf32_round(wvS[i].y);
            Ws[(kc + 2) * WSTRIDE + nrow] = tf32_round(wvS[i].z);
            Ws[(kc + 3) * WSTRIDE + nrow] = tf32_round(wvS[i].w);
        }
    };
    auto MMA = [&](int s) {
        float* As = Asb[s];
        float* Ws = Wsb[s];
#pragma unroll
        for (int ks = 0; ks < 32; ks += 8) {
            uint32_t a[2][4];
#pragma unroll
            for (int mi = 0; mi < 2; mi++) {
                int m = wm + mi * 16 + gid;
                a[mi][0] = __float_as_uint(As[(ks + tig) * 132 + m]);
                a[mi][1] = __float_as_uint(As[(ks + tig) * 132 + m + 8]);
                a[mi][2] = __float_as_uint(As[(ks + tig + 4) * 132 + m]);
                a[mi][3] = __float_as_uint(As[(ks + tig + 4) * 132 + m + 8]);
            }
#pragma unroll
            for (int ni = 0; ni < NF; ni++) {
                int n = wn + ni * 8 + gid;
                uint32_t b0 = __float_as_uint(Ws[(ks + tig) * WSTRIDE + n]);
                uint32_t b1 = __float_as_uint(Ws[(ks + tig + 4) * WSTRIDE + n]);
                mma_tf32(acc[0][ni], a[0], b0, b1);
                mma_tf32(acc[1][ni], a[1], b0, b1);
            }
        }
    };

    LOAD(0);
    STORE(0);
    __syncthreads();
    int s = 0;
#pragma unroll 1
    for (int k0 = 32; k0 < D_MODEL; k0 += 32) {
        LOAD(k0);
        MMA(s);
        STORE(s ^ 1);
        __syncthreads();
        s ^= 1;
    }
    MMA(s);

#pragma unroll
    for (int mi = 0; mi < 2; mi++) {
#pragma unroll
        for (int ni = 0; ni < NF; ni++) {
#pragma unroll
            for (int r = 0; r < 4; r++) {
                int ml = wm + mi * 16 + gid + ((r >> 1) ? 8 : 0);
                int nl = wn + ni * 8 + 2 * tig + (r & 1);
                float v = acc[mi][ni][r];
                if (MODE == 0) {
                    int m = m0 + ml;
                    int n = n_base + nl;
                    int bb = m >> 11, tq = m & 2047;
                    int hh = n >> 6, d = n & 63;
                    g_Qh[(((size_t)bb * N_HEAD + hh) * TQ + tq) * HEAD_DIM + d] =
                        v + bias[n];
                } else if (MODE == 1) {
                    g_Kh[((size_t)bh * L_CTX + m0 + ml) * HEAD_DIM + nl] =
                        v + bias[n_base + nl];
                } else if (MODE == 2) {
                    g_Vh[((size_t)bh * L_CTX + m0 + ml) * HEAD_DIM + nl] =
                        v + bias[n_base + nl];
                } else {
                    Cout[(size_t)(m0 + ml) * D_MODEL + n_base + nl] =
                        v + bias[n_base + nl];
                }
            }
        }
    }
}

// ---------------------------------------------------------------------------
// Flash attention, R4 smem layouts, q-tile = 128 (warp owns 32 rows).
// K fragments loaded once per ks and reused across both m-halves.
// ---------------------------------------------------------------------------
#define AT_THREADS 128
#define OFF_QF   0
#define OFF_KHI  8192
#define OFF_KLO  (8192 + 5120)
#define OFF_VF   (8192 + 2 * 5120)
#define OFF_P    (8192 + 3 * 5120)
#define OFF_MSK  (OFF_P + 4 * 16 * 68)
#define AT_SMEM_BYTES ((OFF_MSK + 512) * 4)

__global__ void __launch_bounds__(128, 2)
attn_kernel(const int* __restrict__ mask) {
    extern __shared__ float sm[];
    float* Qf  = sm + OFF_QF;    // [ks8][mg8][ln32][slot4]
    float* Khi = sm + OFF_KHI;   // R4 layout
    float* Klo = sm + OFF_KLO;
    float* Vf  = sm + OFF_VF;
    float* Pw  = sm + OFF_P;     // per-warp [16][68]
    int*   msk = (int*)(sm + OFF_MSK);

    const int bh = blockIdx.y;
    const int b = bh >> 4, h = bh & 15;
    const int q0 = blockIdx.x * 128;
    const int tid = threadIdx.x;
    const int lane = tid & 31, warp = tid >> 5;
    const int gid = lane >> 2, tig = lane & 3;

    for (int i = tid; i < L_CTX; i += AT_THREADS)
        msk[i] = mask[(size_t)b * TK + h + STRIDE * i];

    // Q tile (128 rows) -> fragment-major smem (R4 scheme, mg 0..7)
    const float* Qb = g_Qh + ((size_t)bh * TQ + q0) * HEAD_DIM;
#pragma unroll
    for (int i = 0; i < 16; i++) {
        int idx = tid + i * AT_THREADS;   // 0..2047
        int row = idx >> 4;               // 0..127
        int dc = (idx & 15) * 4;
        float4 v = *(const float4*)(Qb + row * 64 + dc);
        int mg = row >> 4, mh = (row >> 3) & 1, g = row & 7;
        float vv[4] = {v.x, v.y, v.z, v.w};
#pragma unroll
        for (int e = 0; e < 4; e++) {
            int d = dc + e;
            int ks = d >> 3, kh = (d >> 2) & 1, tg = d & 3;
            int ln = ((g * 4 + tg) + ks * 2) & 31;
            Qf[((ks * 8 + mg) * 32 + ln) * 4 + kh * 2 + mh] = vv[e];
        }
    }

    const float* Kb = g_Kh + (size_t)bh * L_CTX * HEAD_DIM;
    const float* Vb = g_Vh + (size_t)bh * L_CTX * HEAD_DIM;
    float* Pp = Pw + warp * (16 * 68);

    float oacc[2][8][4] = {};
    float M[2][2] = {{-1e30f, -1e30f}, {-1e30f, -1e30f}};
    float Ls[2][2] = {{0.f, 0.f}, {0.f, 0.f}};

#pragma unroll 1
    for (int lt = 0; lt < 8; lt++) {
        __syncthreads();
        // cooperative K (hi/lo) + V tile load (R4 formulas, verbatim)
#pragma unroll
        for (int i = 0; i < 8; i++) {
            int idx = tid + i * AT_THREADS;
            int r = idx >> 4;
            int dc = (idx & 15) * 4;
            float4 kv = *(const float4*)(Kb + (size_t)(lt * 64 + r) * 64 + dc);
            float kk[4] = {kv.x, kv.y, kv.z, kv.w};
#pragma unroll
            for (int e = 0; e < 4; e++) {
                int d = dc + e;
                int ks = d >> 3, kh = (d >> 2) & 1, tg = d & 3;
                int ip = ((ks * 64 + r) * 5 + ((tg + ks) & 3)) * 2 + kh;
                float hi = tf32_round(kk[e]);
                Khi[ip] = hi;
                Klo[ip] = tf32_round(kk[e] - hi);
            }
            float4 vv = *(const float4*)(Vb + (size_t)(lt * 64 + r) * 64 + dc);
            float vl[4] = {vv.x, vv.y, vv.z, vv.w};
            int vks = r >> 3, vkh = (r >> 2) & 1;
            int vte = ((r & 3) + vks) & 3;
#pragma unroll
            for (int e = 0; e < 4; e++)
                Vf[((vks * 64 + (dc + e)) * 5 + vte) * 2 + vkh] = tf32_round(vl[e]);
        }
        __syncthreads();

        // ---- S = Q K^T for both m-halves; K frags loaded ONCE ----
        float sacc[2][8][4] = {};
#pragma unroll
        for (int ks = 0; ks < 8; ks++) {
            uint32_t qh[2][4], ql[2][4];
#pragma unroll
            for (int mi = 0; mi < 2; mi++) {
                float4 qv = *(const float4*)&Qf[((ks * 8 + (warp * 2 + mi)) * 32 +
                                                 ((lane + ks * 2) & 31)) * 4];
                float q4[4] = {qv.x, qv.y, qv.z, qv.w};
#pragma unroll
                for (int j = 0; j < 4; j++) {
                    float hi = tf32_round(q4[j]);
                    qh[mi][j] = __float_as_uint(hi);
                    ql[mi][j] = __float_as_uint(tf32_round(q4[j] - hi));
                }
            }
#pragma unroll
            for (int nh = 0; nh < 2; nh++) {
                float2 khf[4], klf[4];
#pragma unroll
                for (int j = 0; j < 4; j++) {
                    int n = (nh * 4 + j) * 8 + gid;
                    int ip = ((ks * 64 + n) * 5 + ((tig + ks) & 3)) * 2;
                    khf[j] = *(const float2*)&Khi[ip];
                    klf[j] = *(const float2*)&Klo[ip];
                }
#pragma unroll
                for (int mi = 0; mi < 2; mi++) {
#pragma unroll
                    for (int j = 0; j < 4; j++) {
                        int ni = nh * 4 + j;
                        uint32_t b0 = __float_as_uint(khf[j].x);
                        uint32_t b1 = __float_as_uint(khf[j].y);
                        uint32_t c0 = __float_as_uint(klf[j].x);
                        uint32_t c1 = __float_as_uint(klf[j].y);
                        mma_tf32(sacc[mi][ni], qh[mi], b0, b1);
                        mma_tf32(sacc[mi][ni], ql[mi], b0, b1);
                        mma_tf32(sacc[mi][ni], qh[mi], c0, c1);
                    }
                }
            }
        }

        // ---- per m-half: mask + online softmax + P + PV ----
#pragma unroll
        for (int mi = 0; mi < 2; mi++) {
            float mt0 = -1e30f, mt1 = -1e30f;
#pragma unroll
            for (int ni = 0; ni < 8; ni++) {
                int c = lt * 64 + ni * 8 + 2 * tig;
                bool z0 = (msk[c] == 0), z1 = (msk[c + 1] == 0);
                sacc[mi][ni][0] = z0 ? -1e9f : sacc[mi][ni][0] * 0.125f;
                sacc[mi][ni][1] = z1 ? -1e9f : sacc[mi][ni][1] * 0.125f;
                sacc[mi][ni][2] = z0 ? -1e9f : sacc[mi][ni][2] * 0.125f;
                sacc[mi][ni][3] = z1 ? -1e9f : sacc[mi][ni][3] * 0.125f;
                mt0 = fmaxf(mt0, fmaxf(sacc[mi][ni][0], sacc[mi][ni][1]));
                mt1 = fmaxf(mt1, fmaxf(sacc[mi][ni][2], sacc[mi][ni][3]));
            }
            mt0 = fmaxf(mt0, __shfl_xor_sync(0xffffffffu, mt0, 1));
            mt0 = fmaxf(mt0, __shfl_xor_sync(0xffffffffu, mt0, 2));
            mt1 = fmaxf(mt1, __shfl_xor_sync(0xffffffffu, mt1, 1));
            mt1 = fmaxf(mt1, __shfl_xor_sync(0xffffffffu, mt1, 2));

            float Mn0 = fmaxf(M[mi][0], mt0), Mn1 = fmaxf(M[mi][1], mt1);
            float f0 = __expf(M[mi][0] - Mn0), f1 = __expf(M[mi][1] - Mn1);
            float s0 = 0.f, s1 = 0.f;
#pragma unroll
            for (int ni = 0; ni < 8; ni++) {
                int cc = ni * 8 + 2 * tig;
                float p00 = __expf(sacc[mi][ni][0] - Mn0);
                float p01 = __expf(sacc[mi][ni][1] - Mn0);
                float p10 = __expf(sacc[mi][ni][2] - Mn1);
                float p11 = __expf(sacc[mi][ni][3] - Mn1);
                s0 += p00 + p01; s1 += p10 + p11;
                Pp[gid * 68 + cc]           = tf32_round(p00);
                Pp[gid * 68 + cc + 1]       = tf32_round(p01);
                Pp[(gid + 8) * 68 + cc]     = tf32_round(p10);
                Pp[(gid + 8) * 68 + cc + 1] = tf32_round(p11);
            }
            s0 += __shfl_xor_sync(0xffffffffu, s0, 1);
            s0 += __shfl_xor_sync(0xffffffffu, s0, 2);
            s1 += __shfl_xor_sync(0xffffffffu, s1, 1);
            s1 += __shfl_xor_sync(0xffffffffu, s1, 2);
            Ls[mi][0] = Ls[mi][0] * f0 + s0;
            Ls[mi][1] = Ls[mi][1] * f1 + s1;
            M[mi][0] = Mn0; M[mi][1] = Mn1;
#pragma unroll
            for (int ni = 0; ni < 8; ni++) {
                oacc[mi][ni][0] *= f0; oacc[mi][ni][1] *= f0;
                oacc[mi][ni][2] *= f1; oacc[mi][ni][3] *= f1;
            }
            __syncwarp();

            // O += P V (R4 V layout)
#pragma unroll
            for (int ks = 0; ks < 8; ks++) {
                uint32_t a[4];
                a[0] = __float_as_uint(Pp[gid * 68 + ks * 8 + tig]);
                a[1] = __float_as_uint(Pp[(gid + 8) * 68 + ks * 8 + tig]);
                a[2] = __float_as_uint(Pp[gid * 68 + ks * 8 + tig + 4]);
                a[3] = __float_as_uint(Pp[(gid + 8) * 68 + ks * 8 + tig + 4]);
#pragma unroll
                for (int ni = 0; ni < 8; ni++) {
                    int n = ni * 8 + gid;
                    int ip = ((ks * 64 + n) * 5 + ((tig + ks) & 3)) * 2;
                    float2 bv = *(const float2*)&Vf[ip];
                    mma_tf32(oacc[mi][ni], a,
                             __float_as_uint(bv.x), __float_as_uint(bv.y));
                }
            }
            __syncwarp();   // before next mi overwrites Pp
        }
    }

    // ---- epilogue ----
#pragma unroll
    for (int mi = 0; mi < 2; mi++) {
        float inv0 = 1.0f / Ls[mi][0], inv1 = 1.0f / Ls[mi][1];
        int r0 = q0 + warp * 32 + mi * 16 + gid;
#pragma unroll
        for (int ni = 0; ni < 8; ni++) {
            int col = h * 64 + ni * 8 + 2 * tig;
            size_t base0 = ((size_t)b * TQ + r0) * D_MODEL + col;
            *(float2*)&g_ctx[base0] =
                make_float2(oacc[mi][ni][0] * inv0, oacc[mi][ni][1] * inv0);
            *(float2*)&g_ctx[base0 + (size_t)8 * D_MODEL] =
                make_float2(oacc[mi][ni][2] * inv1, oacc[mi][ni][3] * inv1);
        }
    }
}

// ---------------------------------------------------------------------------
extern "C" void kernel_launch(void* const* d_in, const int* in_sizes, int n_in,
                              void* d_out, int out_size) {
    const float* q        = (const float*)d_in[0];
    const float* k        = (const float*)d_in[1];
    const float* v        = (const float*)d_in[2];
    const int*   src_mask = (const int*)d_in[3];
    const float* w_q      = (const float*)d_in[4];
    const float* b_q      = (const float*)d_in[5];
    const float* w_k      = (const float*)d_in[6];
    const float* b_k      = (const float*)d_in[7];
    const float* w_v      = (const float*)d_in[8];
    const float* b_v      = (const float*)d_in[9];
    const float* w_o      = (const float*)d_in[10];
    const float* b_o      = (const float*)d_in[11];
    float* out = (float*)d_out;

    constexpr int PSM_128 = 2 * (32 * 132 + 32 * 132) * 4;   // 67584
    constexpr int PSM_64  = 2 * (32 * 132 + 32 * 68) * 4;    // 51200

    cudaFuncSetAttribute(attn_kernel,
                         cudaFuncAttributeMaxDynamicSharedMemorySize,
                         AT_SMEM_BYTES);
    cudaFuncSetAttribute(tf32_gemm_kernel<128, 0>,
                         cudaFuncAttributeMaxDynamicSharedMemorySize, PSM_128);
    cudaFuncSetAttribute(tf32_gemm_kernel<128, 3>,
                         cudaFuncAttributeMaxDynamicSharedMemorySize, PSM_128);
    cudaFuncSetAttribute(tf32_gemm_kernel<64, 1>,
                         cudaFuncAttributeMaxDynamicSharedMemorySize, PSM_64);
    cudaFuncSetAttribute(tf32_gemm_kernel<64, 2>,
                         cudaFuncAttributeMaxDynamicSharedMemorySize, PSM_64);

    tf32_gemm_kernel<128, 0><<<dim3(D_MODEL / 128, (B_SZ * TQ) / 128), 256,
                               PSM_128>>>(q, w_q, b_q, nullptr);
    tf32_gemm_kernel<64, 1><<<dim3(L_CTX / 128, B_SZ * N_HEAD), 256,
                              PSM_64>>>(k, w_k, b_k, nullptr);
    tf32_gemm_kernel<64, 2><<<dim3(L_CTX / 128, B_SZ * N_HEAD), 256,
                              PSM_64>>>(v, w_v, b_v, nullptr);

    attn_kernel<<<dim3(TQ / 128, B_SZ * N_HEAD), 128, AT_SMEM_BYTES>>>(src_mask);

    tf32_gemm_kernel<128, 3><<<dim3(D_MODEL / 128, (B_SZ * TQ) / 128), 256,
                               PSM_128>>>(nullptr, w_o, b_o, out);
}

// round 7
// speedup vs baseline: 1.7078x; 1.1673x over previous
#include <cuda_runtime.h>
#include <cstdint>

#define D_MODEL 1024
#define N_HEAD 16
#define HEAD_DIM 64
#define B_SZ 4
#define TQ 2048
#define TK 8192
#define STRIDE 16
#define L_CTX 512

__device__ float g_Qh[(size_t)B_SZ * N_HEAD * TQ * HEAD_DIM];
__device__ float g_Kh[(size_t)B_SZ * N_HEAD * L_CTX * HEAD_DIM];
__device__ float g_Vh[(size_t)B_SZ * N_HEAD * L_CTX * HEAD_DIM];
__device__ float g_ctx[(size_t)B_SZ * TQ * D_MODEL];

// ---------------------------------------------------------------------------
__device__ __forceinline__ float tf32_round(float x) {
    uint32_t u;
    asm("cvt.rna.tf32.f32 %0, %1;" : "=r"(u) : "f"(x));
    return __uint_as_float(u);
}

__device__ __forceinline__ void mma_tf32(float* c, const uint32_t* a,
                                         uint32_t b0, uint32_t b1) {
    asm volatile(
        "mma.sync.aligned.m16n8k8.row.col.f32.tf32.tf32.f32 "
        "{%0,%1,%2,%3}, {%4,%5,%6,%7}, {%8,%9}, {%0,%1,%2,%3};\n"
        : "+f"(c[0]), "+f"(c[1]), "+f"(c[2]), "+f"(c[3])
        : "r"(a[0]), "r"(a[1]), "r"(a[2]), "r"(a[3]), "r"(b0), "r"(b1));
}

// ---------------------------------------------------------------------------
// tf32 GEMM. Row-major [row][k] smem (stride 36): vector STS.128 stores,
// conflict-free scalar fragment LDS. 2-stage ping-pong, 1 sync/iter.
// MODE 0: Q proj, 1: K sliced, 2: V sliced, 3: O proj.
// ---------------------------------------------------------------------------
template <int BN, int MODE>
__global__ void __launch_bounds__(256, 2)
tf32_gemm_kernel(const float* __restrict__ Ain,
                 const float* __restrict__ W,
                 const float* __restrict__ bias,
                 float* __restrict__ Cout) {
    extern __shared__ float dsm[];
    constexpr int KS = 36;                    // row stride (32 + 4 pad)
    constexpr int ASTAGE = 128 * KS;
    constexpr int WSTAGE = BN * KS;
    float* Asb[2] = {dsm, dsm + ASTAGE + WSTAGE};
    float* Wsb[2] = {dsm + ASTAGE, dsm + 2 * ASTAGE + WSTAGE};

    const int tid = threadIdx.x;
    const int lane = tid & 31, warp = tid >> 5;
    const int gid = lane >> 2, tig = lane & 3;

    int m0, bh = 0, h = 0, n_base = 0;
    const float* A;
    if (MODE == 1 || MODE == 2) {
        bh = blockIdx.y; int b = bh >> 4; h = bh & 15;
        m0 = blockIdx.x * 128;
        A = Ain + (size_t)b * TK * D_MODEL;
        n_base = h * 64;
    } else {
        m0 = blockIdx.y * 128;
        n_base = blockIdx.x * BN;
        A = (MODE == 3) ? g_ctx : Ain;
    }

    const int wm = (warp >> 1) * 32;
    const int wn = (warp & 1) * (BN / 2);
    constexpr int NF = BN / 16;
    constexpr int WL = BN / 32;

    float acc[2][NF][4] = {};
    float4 avS[4];
    float4 wvS[WL];

    auto LOAD = [&](int k0) {
#pragma unroll
        for (int i = 0; i < 4; i++) {
            int idx = tid + i * 256;
            int row = idx >> 3, kc = (idx & 7) * 4;
            int grow = (MODE == 1 || MODE == 2) ? (h + STRIDE * (m0 + row))
                                                : (m0 + row);
            avS[i] = *(const float4*)(A + (size_t)grow * D_MODEL + k0 + kc);
        }
#pragma unroll
        for (int i = 0; i < WL; i++) {
            int idx = tid + i * 256;
            int nrow = idx >> 3, kc = (idx & 7) * 4;
            wvS[i] = *(const float4*)(W + (size_t)(n_base + nrow) * D_MODEL + k0 + kc);
        }
    };
    auto STORE = [&](int s) {
        float* As = Asb[s];
        float* Ws = Wsb[s];
#pragma unroll
        for (int i = 0; i < 4; i++) {
            int idx = tid + i * 256;
            int row = idx >> 3, kc = (idx & 7) * 4;
            float4 r = make_float4(tf32_round(avS[i].x), tf32_round(avS[i].y),
                                   tf32_round(avS[i].z), tf32_round(avS[i].w));
            *(float4*)&As[row * KS + kc] = r;
        }
#pragma unroll
        for (int i = 0; i < WL; i++) {
            int idx = tid + i * 256;
            int nrow = idx >> 3, kc = (idx & 7) * 4;
            float4 r = make_float4(tf32_round(wvS[i].x), tf32_round(wvS[i].y),
                                   tf32_round(wvS[i].z), tf32_round(wvS[i].w));
            *(float4*)&Ws[nrow * KS + kc] = r;
        }
    };
    auto MMA = [&](int s) {
        float* As = Asb[s];
        float* Ws = Wsb[s];
#pragma unroll
        for (int ks = 0; ks < 32; ks += 8) {
            uint32_t a[2][4];
#pragma unroll
            for (int mi = 0; mi < 2; mi++) {
                int m = wm + mi * 16 + gid;
                a[mi][0] = __float_as_uint(As[m * KS + ks + tig]);
                a[mi][1] = __float_as_uint(As[(m + 8) * KS + ks + tig]);
                a[mi][2] = __float_as_uint(As[m * KS + ks + tig + 4]);
                a[mi][3] = __float_as_uint(As[(m + 8) * KS + ks + tig + 4]);
            }
#pragma unroll
            for (int ni = 0; ni < NF; ni++) {
                int n = wn + ni * 8 + gid;
                uint32_t b0 = __float_as_uint(Ws[n * KS + ks + tig]);
                uint32_t b1 = __float_as_uint(Ws[n * KS + ks + tig + 4]);
                mma_tf32(acc[0][ni], a[0], b0, b1);
                mma_tf32(acc[1][ni], a[1], b0, b1);
            }
        }
    };

    LOAD(0);
    STORE(0);
    __syncthreads();
    int s = 0;
#pragma unroll 1
    for (int k0 = 32; k0 < D_MODEL; k0 += 32) {
        LOAD(k0);
        MMA(s);
        STORE(s ^ 1);
        __syncthreads();
        s ^= 1;
    }
    MMA(s);

#pragma unroll
    for (int mi = 0; mi < 2; mi++) {
#pragma unroll
        for (int ni = 0; ni < NF; ni++) {
#pragma unroll
            for (int r = 0; r < 4; r++) {
                int ml = wm + mi * 16 + gid + ((r >> 1) ? 8 : 0);
                int nl = wn + ni * 8 + 2 * tig + (r & 1);
                float v = acc[mi][ni][r];
                if (MODE == 0) {
                    int m = m0 + ml;
                    int n = n_base + nl;
                    int bb = m >> 11, tq = m & 2047;
                    int hh = n >> 6, d = n & 63;
                    g_Qh[(((size_t)bb * N_HEAD + hh) * TQ + tq) * HEAD_DIM + d] =
                        v + bias[n];
                } else if (MODE == 1) {
                    g_Kh[((size_t)bh * L_CTX + m0 + ml) * HEAD_DIM + nl] =
                        v + bias[n_base + nl];
                } else if (MODE == 2) {
                    g_Vh[((size_t)bh * L_CTX + m0 + ml) * HEAD_DIM + nl] =
                        v + bias[n_base + nl];
                } else {
                    Cout[(size_t)(m0 + ml) * D_MODEL + n_base + nl] =
                        v + bias[n_base + nl];
                }
            }
        }
    }
}

// ---------------------------------------------------------------------------
// Flash attention (unchanged from R6).
// ---------------------------------------------------------------------------
#define AT_THREADS 128
#define OFF_QF   0
#define OFF_KHI  8192
#define OFF_KLO  (8192 + 5120)
#define OFF_VF   (8192 + 2 * 5120)
#define OFF_P    (8192 + 3 * 5120)
#define OFF_MSK  (OFF_P + 4 * 16 * 68)
#define AT_SMEM_BYTES ((OFF_MSK + 512) * 4)

__global__ void __launch_bounds__(128, 2)
attn_kernel(const int* __restrict__ mask) {
    extern __shared__ float sm[];
    float* Qf  = sm + OFF_QF;
    float* Khi = sm + OFF_KHI;
    float* Klo = sm + OFF_KLO;
    float* Vf  = sm + OFF_VF;
    float* Pw  = sm + OFF_P;
    int*   msk = (int*)(sm + OFF_MSK);

    const int bh = blockIdx.y;
    const int b = bh >> 4, h = bh & 15;
    const int q0 = blockIdx.x * 128;
    const int tid = threadIdx.x;
    const int lane = tid & 31, warp = tid >> 5;
    const int gid = lane >> 2, tig = lane & 3;

    for (int i = tid; i < L_CTX; i += AT_THREADS)
        msk[i] = mask[(size_t)b * TK + h + STRIDE * i];

    const float* Qb = g_Qh + ((size_t)bh * TQ + q0) * HEAD_DIM;
#pragma unroll
    for (int i = 0; i < 16; i++) {
        int idx = tid + i * AT_THREADS;
        int row = idx >> 4;
        int dc = (idx & 15) * 4;
        float4 v = *(const float4*)(Qb + row * 64 + dc);
        int mg = row >> 4, mh = (row >> 3) & 1, g = row & 7;
        float vv[4] = {v.x, v.y, v.z, v.w};
#pragma unroll
        for (int e = 0; e < 4; e++) {
            int d = dc + e;
            int ks = d >> 3, kh = (d >> 2) & 1, tg = d & 3;
            int ln = ((g * 4 + tg) + ks * 2) & 31;
            Qf[((ks * 8 + mg) * 32 + ln) * 4 + kh * 2 + mh] = vv[e];
        }
    }

    const float* Kb = g_Kh + (size_t)bh * L_CTX * HEAD_DIM;
    const float* Vb = g_Vh + (size_t)bh * L_CTX * HEAD_DIM;
    float* Pp = Pw + warp * (16 * 68);

    float oacc[2][8][4] = {};
    float M[2][2] = {{-1e30f, -1e30f}, {-1e30f, -1e30f}};
    float Ls[2][2] = {{0.f, 0.f}, {0.f, 0.f}};

#pragma unroll 1
    for (int lt = 0; lt < 8; lt++) {
        __syncthreads();
#pragma unroll
        for (int i = 0; i < 8; i++) {
            int idx = tid + i * AT_THREADS;
            int r = idx >> 4;
            int dc = (idx & 15) * 4;
            float4 kv = *(const float4*)(Kb + (size_t)(lt * 64 + r) * 64 + dc);
            float kk[4] = {kv.x, kv.y, kv.z, kv.w};
#pragma unroll
            for (int e = 0; e < 4; e++) {
                int d = dc + e;
                int ks = d >> 3, kh = (d >> 2) & 1, tg = d & 3;
                int ip = ((ks * 64 + r) * 5 + ((tg + ks) & 3)) * 2 + kh;
                float hi = tf32_round(kk[e]);
                Khi[ip] = hi;
                Klo[ip] = tf32_round(kk[e] - hi);
            }
            float4 vv = *(const float4*)(Vb + (size_t)(lt * 64 + r) * 64 + dc);
            float vl[4] = {vv.x, vv.y, vv.z, vv.w};
            int vks = r >> 3, vkh = (r >> 2) & 1;
            int vte = ((r & 3) + vks) & 3;
#pragma unroll
            for (int e = 0; e < 4; e++)
                Vf[((vks * 64 + (dc + e)) * 5 + vte) * 2 + vkh] = tf32_round(vl[e]);
        }
        __syncthreads();

        float sacc[2][8][4] = {};
#pragma unroll
        for (int ks = 0; ks < 8; ks++) {
            uint32_t qh[2][4], ql[2][4];
#pragma unroll
            for (int mi = 0; mi < 2; mi++) {
                float4 qv = *(const float4*)&Qf[((ks * 8 + (warp * 2 + mi)) * 32 +
                                                 ((lane + ks * 2) & 31)) * 4];
                float q4[4] = {qv.x, qv.y, qv.z, qv.w};
#pragma unroll
                for (int j = 0; j < 4; j++) {
                    float hi = tf32_round(q4[j]);
                    qh[mi][j] = __float_as_uint(hi);
                    ql[mi][j] = __float_as_uint(tf32_round(q4[j] - hi));
                }
            }
#pragma unroll
            for (int nh = 0; nh < 2; nh++) {
                float2 khf[4], klf[4];
#pragma unroll
                for (int j = 0; j < 4; j++) {
                    int n = (nh * 4 + j) * 8 + gid;
                    int ip = ((ks * 64 + n) * 5 + ((tig + ks) & 3)) * 2;
                    khf[j] = *(const float2*)&Khi[ip];
                    klf[j] = *(const float2*)&Klo[ip];
                }
#pragma unroll
                for (int mi = 0; mi < 2; mi++) {
#pragma unroll
                    for (int j = 0; j < 4; j++) {
                        int ni = nh * 4 + j;
                        uint32_t b0 = __float_as_uint(khf[j].x);
                        uint32_t b1 = __float_as_uint(khf[j].y);
                        uint32_t c0 = __float_as_uint(klf[j].x);
                        uint32_t c1 = __float_as_uint(klf[j].y);
                        mma_tf32(sacc[mi][ni], qh[mi], b0, b1);
                        mma_tf32(sacc[mi][ni], ql[mi], b0, b1);
                        mma_tf32(sacc[mi][ni], qh[mi], c0, c1);
                    }
                }
            }
        }

#pragma unroll
        for (int mi = 0; mi < 2; mi++) {
            float mt0 = -1e30f, mt1 = -1e30f;
#pragma unroll
            for (int ni = 0; ni < 8; ni++) {
                int c = lt * 64 + ni * 8 + 2 * tig;
                bool z0 = (msk[c] == 0), z1 = (msk[c + 1] == 0);
                sacc[mi][ni][0] = z0 ? -1e9f : sacc[mi][ni][0] * 0.125f;
                sacc[mi][ni][1] = z1 ? -1e9f : sacc[mi][ni][1] * 0.125f;
                sacc[mi][ni][2] = z0 ? -1e9f : sacc[mi][ni][2] * 0.125f;
                sacc[mi][ni][3] = z1 ? -1e9f : sacc[mi][ni][3] * 0.125f;
                mt0 = fmaxf(mt0, fmaxf(sacc[mi][ni][0], sacc[mi][ni][1]));
                mt1 = fmaxf(mt1, fmaxf(sacc[mi][ni][2], sacc[mi][ni][3]));
            }
            mt0 = fmaxf(mt0, __shfl_xor_sync(0xffffffffu, mt0, 1));
            mt0 = fmaxf(mt0, __shfl_xor_sync(0xffffffffu, mt0, 2));
            mt1 = fmaxf(mt1, __shfl_xor_sync(0xffffffffu, mt1, 1));
            mt1 = fmaxf(mt1, __shfl_xor_sync(0xffffffffu, mt1, 2));

            float Mn0 = fmaxf(M[mi][0], mt0), Mn1 = fmaxf(M[mi][1], mt1);
            float f0 = __expf(M[mi][0] - Mn0), f1 = __expf(M[mi][1] - Mn1);
            float s0 = 0.f, s1 = 0.f;
#pragma unroll
            for (int ni = 0; ni < 8; ni++) {
                int cc = ni * 8 + 2 * tig;
                float p00 = __expf(sacc[mi][ni][0] - Mn0);
                float p01 = __expf(sacc[mi][ni][1] - Mn0);
                float p10 = __expf(sacc[mi][ni][2] - Mn1);
                float p11 = __expf(sacc[mi][ni][3] - Mn1);
                s0 += p00 + p01; s1 += p10 + p11;
                Pp[gid * 68 + cc]           = tf32_round(p00);
                Pp[gid * 68 + cc + 1]       = tf32_round(p01);
                Pp[(gid + 8) * 68 + cc]     = tf32_round(p10);
                Pp[(gid + 8) * 68 + cc + 1] = tf32_round(p11);
            }
            s0 += __shfl_xor_sync(0xffffffffu, s0, 1);
            s0 += __shfl_xor_sync(0xffffffffu, s0, 2);
            s1 += __shfl_xor_sync(0xffffffffu, s1, 1);
            s1 += __shfl_xor_sync(0xffffffffu, s1, 2);
            Ls[mi][0] = Ls[mi][0] * f0 + s0;
            Ls[mi][1] = Ls[mi][1] * f1 + s1;
            M[mi][0] = Mn0; M[mi][1] = Mn1;
#pragma unroll
            for (int ni = 0; ni < 8; ni++) {
                oacc[mi][ni][0] *= f0; oacc[mi][ni][1] *= f0;
                oacc[mi][ni][2] *= f1; oacc[mi][ni][3] *= f1;
            }
            __syncwarp();

#pragma unroll
            for (int ks = 0; ks < 8; ks++) {
                uint32_t a[4];
                a[0] = __float_as_uint(Pp[gid * 68 + ks * 8 + tig]);
                a[1] = __float_as_uint(Pp[(gid + 8) * 68 + ks * 8 + tig]);
                a[2] = __float_as_uint(Pp[gid * 68 + ks * 8 + tig + 4]);
                a[3] = __float_as_uint(Pp[(gid + 8) * 68 + ks * 8 + tig + 4]);
#pragma unroll
                for (int ni = 0; ni < 8; ni++) {
                    int n = ni * 8 + gid;
                    int ip = ((ks * 64 + n) * 5 + ((tig + ks) & 3)) * 2;
                    float2 bv = *(const float2*)&Vf[ip];
                    mma_tf32(oacc[mi][ni], a,
                             __float_as_uint(bv.x), __float_as_uint(bv.y));
                }
            }
            __syncwarp();
        }
    }

#pragma unroll
    for (int mi = 0; mi < 2; mi++) {
        float inv0 = 1.0f / Ls[mi][0], inv1 = 1.0f / Ls[mi][1];
        int r0 = q0 + warp * 32 + mi * 16 + gid;
#pragma unroll
        for (int ni = 0; ni < 8; ni++) {
            int col = h * 64 + ni * 8 + 2 * tig;
            size_t base0 = ((size_t)b * TQ + r0) * D_MODEL + col;
            *(float2*)&g_ctx[base0] =
                make_float2(oacc[mi][ni][0] * inv0, oacc[mi][ni][1] * inv0);
            *(float2*)&g_ctx[base0 + (size_t)8 * D_MODEL] =
                make_float2(oacc[mi][ni][2] * inv1, oacc[mi][ni][3] * inv1);
        }
    }
}

// ---------------------------------------------------------------------------
extern "C" void kernel_launch(void* const* d_in, const int* in_sizes, int n_in,
                              void* d_out, int out_size) {
    const float* q        = (const float*)d_in[0];
    const float* k        = (const float*)d_in[1];
    const float* v        = (const float*)d_in[2];
    const int*   src_mask = (const int*)d_in[3];
    const float* w_q      = (const float*)d_in[4];
    const float* b_q      = (const float*)d_in[5];
    const float* w_k      = (const float*)d_in[6];
    const float* b_k      = (const float*)d_in[7];
    const float* w_v      = (const float*)d_in[8];
    const float* b_v      = (const float*)d_in[9];
    const float* w_o      = (const float*)d_in[10];
    const float* b_o      = (const float*)d_in[11];
    float* out = (float*)d_out;

    constexpr int PSM_128 = 2 * (128 * 36 + 128 * 36) * 4;   // 73728
    constexpr int PSM_64  = 2 * (128 * 36 + 64 * 36) * 4;    // 55296

    cudaFuncSetAttribute(attn_kernel,
                         cudaFuncAttributeMaxDynamicSharedMemorySize,
                         AT_SMEM_BYTES);
    cudaFuncSetAttribute(tf32_gemm_kernel<128, 0>,
                         cudaFuncAttributeMaxDynamicSharedMemorySize, PSM_128);
    cudaFuncSetAttribute(tf32_gemm_kernel<128, 3>,
                         cudaFuncAttributeMaxDynamicSharedMemorySize, PSM_128);
    cudaFuncSetAttribute(tf32_gemm_kernel<64, 1>,
                         cudaFuncAttributeMaxDynamicSharedMemorySize, PSM_64);
    cudaFuncSetAttribute(tf32_gemm_kernel<64, 2>,
                         cudaFuncAttributeMaxDynamicSharedMemorySize, PSM_64);

    tf32_gemm_kernel<128, 0><<<dim3(D_MODEL / 128, (B_SZ * TQ) / 128), 256,
                               PSM_128>>>(q, w_q, b_q, nullptr);
    tf32_gemm_kernel<64, 1><<<dim3(L_CTX / 128, B_SZ * N_HEAD), 256,
                              PSM_64>>>(k, w_k, b_k, nullptr);
    tf32_gemm_kernel<64, 2><<<dim3(L_CTX / 128, B_SZ * N_HEAD), 256,
                              PSM_64>>>(v, w_v, b_v, nullptr);

    attn_kernel<<<dim3(TQ / 128, B_SZ * N_HEAD), 128, AT_SMEM_BYTES>>>(src_mask);

    tf32_gemm_kernel<128, 3><<<dim3(D_MODEL / 128, (B_SZ * TQ) / 128), 256,
                               PSM_128>>>(nullptr, w_o, b_o, out);
}